// round 15
// baseline (speedup 1.0000x reference)
#include <cuda_runtime.h>

#define FULL 0xffffffffu

// ---------------- scratch ----------------------------------------------------
__device__ float g_F[8 * 81];     // grid evaluations of <Z_j>, layout [j][n]

// ---------------- warp statevector simulation (gridsim only) ----------------
struct St { float2 a[8]; };

__device__ __forceinline__ float2 shxor(float2 v, int m) {
    float2 r;
    r.x = __shfl_xor_sync(FULL, v.x, m);
    r.y = __shfl_xor_sync(FULL, v.y, m);
    return r;
}

template<int Q>
__device__ __forceinline__ void gateRY(St& st, float c, float s, int lane) {
    constexpr int lm = 1 << (4 - Q);
    float sg = (lane & lm) ? s : -s;
#pragma unroll
    for (int m = 0; m < 8; ++m) {
        float2 o = shxor(st.a[m], lm);
        float2 a = st.a[m];
        st.a[m] = make_float2(c * a.x + sg * o.x, c * a.y + sg * o.y);
    }
}

template<int Q>
__device__ __forceinline__ void gateRX(St& st, float c, float s, int lane) {
    if constexpr (Q >= 5) {
        constexpr int bit = 1 << (7 - Q);
#pragma unroll
        for (int m = 0; m < 8; ++m) {
            if ((m & bit) == 0) {
                float2 a = st.a[m], b = st.a[m | bit];
                st.a[m]       = make_float2(c * a.x + s * b.y, c * a.y - s * b.x);
                st.a[m | bit] = make_float2(c * b.x + s * a.y, c * b.y - s * a.x);
            }
        }
    } else {
        constexpr int lm = 1 << (4 - Q);
#pragma unroll
        for (int m = 0; m < 8; ++m) {
            float2 o = shxor(st.a[m], lm);
            float2 a = st.a[m];
            st.a[m] = make_float2(c * a.x + s * o.y, c * a.y - s * o.x);
        }
    }
}

template<int Q>
__device__ __forceinline__ void gateRZ(St& st, float c, float s, int lane) {
    if constexpr (Q >= 5) {
        constexpr int bit = 1 << (7 - Q);
#pragma unroll
        for (int m = 0; m < 8; ++m) {
            float f = (m & bit) ? s : -s;
            float2 a = st.a[m];
            st.a[m] = make_float2(c * a.x - f * a.y, c * a.y + f * a.x);
        }
    } else {
        constexpr int lm = 1 << (4 - Q);
        float f = (lane & lm) ? s : -s;
#pragma unroll
        for (int m = 0; m < 8; ++m) {
            float2 a = st.a[m];
            st.a[m] = make_float2(c * a.x - f * a.y, c * a.y + f * a.x);
        }
    }
}

// Fused CNOT·RY·CNOT (round-10 derivation)
template<int J>
__device__ __forceinline__ void fusedW(St& st, float c, float s, int lane) {
    if constexpr (J <= 3) {
        constexpr int cm = 1 << (4 - J);
        constexpr int tm = 1 << (3 - J);
        float sg = (lane & cm) ? s : -s;
#pragma unroll
        for (int m = 0; m < 8; ++m) {
            float2 o = shxor(st.a[m], cm | tm);
            float2 a = st.a[m];
            st.a[m] = make_float2(c * a.x + sg * o.x, c * a.y + sg * o.y);
        }
    } else if constexpr (J == 4) {
        float sg = (lane & 1) ? s : -s;
        float2 o[8];
#pragma unroll
        for (int m = 0; m < 8; ++m) o[m] = shxor(st.a[m ^ 4], 1);
#pragma unroll
        for (int m = 0; m < 8; ++m) {
            float2 a = st.a[m];
            st.a[m] = make_float2(c * a.x + sg * o[m].x, c * a.y + sg * o[m].y);
        }
    } else if constexpr (J == 5 || J == 6) {
        constexpr int cmask = (J == 5) ? 4 : 2;
        constexpr int xmask = (J == 5) ? 6 : 3;
        float2 old[8];
#pragma unroll
        for (int m = 0; m < 8; ++m) old[m] = st.a[m];
#pragma unroll
        for (int m = 0; m < 8; ++m) {
            float sg = (m & cmask) ? s : -s;
            st.a[m] = make_float2(c * old[m].x + sg * old[m ^ xmask].x,
                                  c * old[m].y + sg * old[m ^ xmask].y);
        }
    } else {
        int bc = (lane >> 4) & 1;
        float2 old[8];
#pragma unroll
        for (int m = 0; m < 8; ++m) old[m] = st.a[m];
#pragma unroll
        for (int m = 0; m < 8; ++m) {
            float sg = ((bc ^ (m & 1)) != 0) ? s : -s;
            st.a[m] = make_float2(c * old[m].x + sg * old[m ^ 1].x,
                                  c * old[m].y + sg * old[m ^ 1].y);
        }
    }
}

template<int J>
__device__ __forceinline__ void ansatzStep(St& st, const float* cw, const float* sw, int lane) {
    float c = cw[J], s = sw[J];
    gateRX<J>(st, c, s, lane);
    fusedW<J>(st, c, s, lane);
    gateRZ<J>(st, c, s, lane);
}

__device__ __forceinline__ void ansatz(St& st, const float* cw, const float* sw, int lane) {
    ansatzStep<0>(st, cw, sw, lane);
    ansatzStep<1>(st, cw, sw, lane);
    ansatzStep<2>(st, cw, sw, lane);
    ansatzStep<3>(st, cw, sw, lane);
    ansatzStep<4>(st, cw, sw, lane);
    ansatzStep<5>(st, cw, sw, lane);
    ansatzStep<6>(st, cw, sw, lane);
    ansatzStep<7>(st, cw, sw, lane);
}

// ---------------- kernel 1: 81 grid circuits ---------------------------------
__global__ void gridsim_kernel(const float* __restrict__ weights,
                               const float* __restrict__ db,
                               float* __restrict__ out) {
    __shared__ float cw[24], sw[24];
    int lane = threadIdx.x;

    if (blockIdx.x == 0) out[lane] = db[0];   // seed output with bias

    if (lane < 24) {
        const float TWO_PI = 6.28318530717958647692f;
        float w = weights[lane];
        float wm = fmodf(w, TWO_PI);
        if (wm < 0.f) wm += TWO_PI;
        float sv, cv;
        __sincosf(0.5f * wm, &sv, &cv);
        cw[lane] = cv;
        sw[lane] = sv;
    }
    __syncwarp();

    St st;
#pragma unroll
    for (int m = 0; m < 8; ++m) st.a[m] = make_float2(0.f, 0.f);
    if (lane == 0) st.a[0] = make_float2(1.f, 0.f);
    ansatz(st, &cw[0], &sw[0], lane);

    const float GC[3] = {1.f, 0.70710678118654752440f, 0.f};
    const float GS[3] = {0.f, 0.70710678118654752440f, 1.f};
    int n = blockIdx.x;
    int k0 = n / 27, k1 = (n / 9) % 3, k2 = (n / 3) % 3, k3 = n % 3;
    gateRY<0>(st, GC[k0], GS[k0], lane);
    gateRY<1>(st, GC[k1], GS[k1], lane);
    gateRY<2>(st, GC[k2], GS[k2], lane);
    gateRY<3>(st, GC[k3], GS[k3], lane);

    ansatz(st, &cw[8],  &sw[8],  lane);
    ansatz(st, &cw[16], &sw[16], lane);

    float vj[8];
#pragma unroll
    for (int j = 0; j < 8; ++j) vj[j] = 0.f;
#pragma unroll
    for (int m = 0; m < 8; ++m) {
        float2 a = st.a[m];
        float p = a.x * a.x + a.y * a.y;
        int idx = (lane << 3) | m;
#pragma unroll
        for (int j = 0; j < 8; ++j) vj[j] += ((idx >> (7 - j)) & 1) ? -p : p;
    }
#pragma unroll
    for (int j = 0; j < 8; ++j) {
#pragma unroll
        for (int o = 16; o; o >>= 1) vj[j] += __shfl_xor_sync(FULL, vj[j], o);
    }
    if (lane == 0) {
#pragma unroll
        for (int j = 0; j < 8; ++j) g_F[j * 81 + n] = vj[j];
    }
}

// ---------------- kernel 2: layer1 + layer2 + pool + dense (dual basis) -----
// 512 threads; thread = (channel = t&7, 2 positions 2q/2q+1).
// Coefficient rows padded 9 -> 12 floats (48B) so each row = 3x LDS.128.
#define CH 128
#define NP (CH + 3)    // 131 layer-1 values (halo)
#define NX (CH + 6)    // 134 x-sincos values
#define ROWP 12        // padded row stride (floats)

// per-axis Lagrange-trig dual basis from (cos a, sin a)
__device__ __forceinline__ void lag3(float cv, float sv, float* e) {
    e[0] = 0.5f * (1.f + cv - sv);
    e[1] = sv;
    e[2] = 0.5f * (1.f - cv - sv);
}

// dot of a padded row (3 x float4, 9 used) with t[9]
__device__ __forceinline__ float dot9(const float4* rv, const float* t) {
    float4 A = rv[0], B = rv[1], C = rv[2];
    float d = A.x * t[0];
    d = fmaf(A.y, t[1], d);
    d = fmaf(A.z, t[2], d);
    d = fmaf(A.w, t[3], d);
    d = fmaf(B.x, t[4], d);
    d = fmaf(B.y, t[5], d);
    d = fmaf(B.z, t[6], d);
    d = fmaf(B.w, t[7], d);
    d = fmaf(C.x, t[8], d);
    return d;
}

__global__ void __launch_bounds__(512) fused_kernel(const float* __restrict__ x,
                                                    const float* __restrict__ dw,
                                                    float* __restrict__ out) {
    __shared__ __align__(16) float coefp[8 * 9 * ROWP];   // padded [ch][9][12]
    __shared__ float xc[NX], xs[NX];     // sincos of input window
    __shared__ float ac[NP], as_[NP];    // sincos of layer-1 relu values
    __shared__ float red[16];

    int t = threadIdx.x;
    int lane = t & 31;
    int warp = t >> 5;
    int b = blockIdx.y;
    int s0 = blockIdx.x * CH;

    // --- load grid values into padded rows: row = ch*9+i, pad cols 9..11 = 0
    for (int k = t; k < 8 * 9 * ROWP; k += 512) {
        int row = k / ROWP, l = k - row * ROWP;
        coefp[k] = (l < 9) ? g_F[row * 9 + l] : 0.f;
    }
    // --- sincos of x window: x index l = s0-2+k ---
    if (t < NX) {
        int l = s0 - 2 + t;
        float cv = 1.f, sv = 0.f;
        if (l >= 0 && l < 1024) __sincosf(x[b * 1024 + l], &sv, &cv);
        xc[t] = cv; xs[t] = sv;
    }
    __syncthreads();

    // --- layer 1: thread-per-position (p = s0 - 1 + t), t < NP=131 ---
    if (t < NP) {
        int p = s0 - 1 + t;
        float cv = 1.f, sv = 0.f;          // OOB position -> angle 0
        if (p >= 0 && p < 1023) {
            float e0[3], e1[3], t23[9];
            lag3(xc[t], xs[t], e0);
            lag3(xc[t + 1], xs[t + 1], e1);
            {
                float e2[3], e3[3];
                lag3(xc[t + 2], xs[t + 2], e2);
                lag3(xc[t + 3], xs[t + 3], e3);
#pragma unroll
                for (int i = 0; i < 3; ++i)
#pragma unroll
                    for (int j = 0; j < 3; ++j) t23[i * 3 + j] = e2[i] * e3[j];
            }
            float v = 0.f;
#pragma unroll
            for (int i = 0; i < 9; ++i) {
                const float4* rv = reinterpret_cast<const float4*>(&coefp[i * ROWP]);
                v = fmaf(e0[i / 3] * e1[i % 3], dot9(rv, t23), v);
            }
            __sincosf(fmaxf(v, 0.f), &sv, &cv);
        }
        ac[t] = cv; as_[t] = sv;
    }
    __syncthreads();

    // --- layer 2: thread = (channel, 2 positions); vectorized row loads ---
    int ch = t & 7;
    int q  = t >> 3;                     // 0..63 -> local positions 2q, 2q+1
    int pA = 2 * q, pB = 2 * q + 1;

    float e0a[3], e1a[3], e0b[3], e1b[3];
    lag3(ac[pA],     as_[pA],     e0a);
    lag3(ac[pA + 1], as_[pA + 1], e1a);
    lag3(ac[pB],     as_[pB],     e0b);
    lag3(ac[pB + 1], as_[pB + 1], e1b);

    float t23a[9], t23b[9];
    {
        float e2[3], e3[3];
        lag3(ac[pA + 2], as_[pA + 2], e2);
        lag3(ac[pA + 3], as_[pA + 3], e3);
#pragma unroll
        for (int i = 0; i < 3; ++i)
#pragma unroll
            for (int j = 0; j < 3; ++j) t23a[i * 3 + j] = e2[i] * e3[j];
        lag3(ac[pB + 2], as_[pB + 2], e2);
        lag3(ac[pB + 3], as_[pB + 3], e3);
#pragma unroll
        for (int i = 0; i < 3; ++i)
#pragma unroll
            for (int j = 0; j < 3; ++j) t23b[i * 3 + j] = e2[i] * e3[j];
    }

    const float* scp = &coefp[ch * 9 * ROWP];
    float acc0 = 0.f, acc1 = 0.f;
#pragma unroll
    for (int i = 0; i < 9; ++i) {
        const float4* rv = reinterpret_cast<const float4*>(&scp[i * ROWP]);
        float4 A = rv[0], B = rv[1], C = rv[2];       // one row: 3x LDS.128
        float pa = A.x * t23a[0], pb = A.x * t23b[0];
        pa = fmaf(A.y, t23a[1], pa);  pb = fmaf(A.y, t23b[1], pb);
        pa = fmaf(A.z, t23a[2], pa);  pb = fmaf(A.z, t23b[2], pb);
        pa = fmaf(A.w, t23a[3], pa);  pb = fmaf(A.w, t23b[3], pb);
        pa = fmaf(B.x, t23a[4], pa);  pb = fmaf(B.x, t23b[4], pb);
        pa = fmaf(B.y, t23a[5], pa);  pb = fmaf(B.y, t23b[5], pb);
        pa = fmaf(B.z, t23a[6], pa);  pb = fmaf(B.z, t23b[6], pb);
        pa = fmaf(B.w, t23a[7], pa);  pb = fmaf(B.w, t23b[7], pb);
        pa = fmaf(C.x, t23a[8], pa);  pb = fmaf(C.x, t23b[8], pb);
        acc0 = fmaf(e0a[i / 3] * e1a[i % 3], pa, acc0);
        acc1 = fmaf(e0b[i / 3] * e1b[i % 3], pb, acc1);
    }

    // channel max across octet (warp-uniform shuffles)
    acc0 = fmaxf(acc0, __shfl_xor_sync(FULL, acc0, 1));
    acc0 = fmaxf(acc0, __shfl_xor_sync(FULL, acc0, 2));
    acc0 = fmaxf(acc0, __shfl_xor_sync(FULL, acc0, 4));
    acc1 = fmaxf(acc1, __shfl_xor_sync(FULL, acc1, 1));
    acc1 = fmaxf(acc1, __shfl_xor_sync(FULL, acc1, 2));
    acc1 = fmaxf(acc1, __shfl_xor_sync(FULL, acc1, 4));

    // dense contributions (relu(max) == max(relu))
    float contrib = 0.f;
    if (ch == 0) {
        int sA = s0 + pA, sB = s0 + pB;
        if (sA < 1022) contrib += fmaxf(acc0, 0.f) * dw[sA];
        if (sB < 1022) contrib += fmaxf(acc1, 0.f) * dw[sB];
    }
    contrib += __shfl_xor_sync(FULL, contrib, 8);
    contrib += __shfl_xor_sync(FULL, contrib, 16);
    if (lane == 0) red[warp] = contrib;
    __syncthreads();
    if (warp == 0) {
        float r = (lane < 16) ? red[lane] : 0.f;
        r += __shfl_xor_sync(FULL, r, 1);
        r += __shfl_xor_sync(FULL, r, 2);
        r += __shfl_xor_sync(FULL, r, 4);
        r += __shfl_xor_sync(FULL, r, 8);
        if (lane == 0) atomicAdd(&out[b], r);
    }
}

// ---------------- launch ------------------------------------------------------
extern "C" void kernel_launch(void* const* d_in, const int* in_sizes, int n_in,
                              void* d_out, int out_size) {
    const float* x       = (const float*)d_in[0];   // (32,1024,1)
    const float* weights = (const float*)d_in[1];   // (3,8)
    const float* dw      = (const float*)d_in[2];   // (1022,1)
    const float* db      = (const float*)d_in[3];   // (1,)
    float* out = (float*)d_out;                     // (32,1)

    gridsim_kernel<<<81, 32>>>(weights, db, out);
    dim3 g((1022 + CH - 1) / CH, 32);               // (8, 32)
    fused_kernel<<<g, 512>>>(x, dw, out);
}